// round 1
// baseline (speedup 1.0000x reference)
#include <cuda_runtime.h>
#include <cuda_bf16.h>
#include <math.h>

#define B_ 4
#define S_ 2048
#define HID_ 2048
#define H_ 16
#define KV_ 4
#define D_ 128
#define ROT_ 32
#define GROUPS_ (H_/KV_)
#define NEG_ (-1000000000.0f)
#define SCALE_ 0.08838834764831845f   // D^-0.5

// ---------------- scratch (device globals; no allocations allowed) ----------
__device__ float g_qg   [(size_t)B_*S_*H_*2*D_];   // [B*S, H*2D]  q|gate
__device__ float g_kproj[(size_t)B_*S_*KV_*D_];    // [B*S, KV*D]
__device__ float g_vproj[(size_t)B_*S_*KV_*D_];    // [B*S, KV*D]
__device__ float g_q    [(size_t)B_*H_*S_*D_];     // [B,H,S,D]
__device__ float g_k    [(size_t)B_*KV_*S_*D_];    // [B,KV,S,D]
__device__ float g_v    [(size_t)B_*KV_*S_*D_];    // [B,KV,S,D]
__device__ float g_attn [(size_t)B_*H_*S_*D_];     // [B,H,S,D]
__device__ float g_gated[(size_t)B_*S_*H_*D_];     // [B*S, H*D]

// ---------------- classic 128x128x8 SGEMM, fp32, row-major ------------------
// A: [M,K], B: [K,N], C: [M,N]. Requires M%128==0, N%128==0, K%8==0.
__global__ __launch_bounds__(256)
void sgemm128(const float* __restrict__ A, const float* __restrict__ B,
              float* __restrict__ C, int M, int N, int K) {
    __shared__ float As[8][128];
    __shared__ float Bs[8][128];
    int tid = threadIdx.x;

    const float* Ab = A + (size_t)blockIdx.y * 128 * K;
    const float* Bb = B + (size_t)blockIdx.x * 128;
    float*       Cb = C + (size_t)blockIdx.y * 128 * N + (size_t)blockIdx.x * 128;

    int aRow = tid >> 1;            // 0..127
    int aCol = (tid & 1) << 2;      // 0 or 4
    int bRow = tid >> 5;            // 0..7
    int bCol = (tid & 31) << 2;     // 0..124

    int tRow = (tid >> 4) << 3;     // 16x16 thread grid, 8x8 each
    int tCol = (tid & 15) << 3;

    float acc[8][8];
    #pragma unroll
    for (int i = 0; i < 8; i++)
        #pragma unroll
        for (int j = 0; j < 8; j++) acc[i][j] = 0.f;

    for (int k0 = 0; k0 < K; k0 += 8) {
        float4 a4 = *(const float4*)(Ab + (size_t)aRow * K + k0 + aCol);
        As[aCol + 0][aRow] = a4.x;
        As[aCol + 1][aRow] = a4.y;
        As[aCol + 2][aRow] = a4.z;
        As[aCol + 3][aRow] = a4.w;
        *(float4*)(&Bs[bRow][bCol]) = *(const float4*)(Bb + (size_t)(k0 + bRow) * N + bCol);
        __syncthreads();
        #pragma unroll
        for (int kk = 0; kk < 8; kk++) {
            float4 a0 = *(const float4*)&As[kk][tRow];
            float4 a1 = *(const float4*)&As[kk][tRow + 4];
            float4 b0 = *(const float4*)&Bs[kk][tCol];
            float4 b1 = *(const float4*)&Bs[kk][tCol + 4];
            float ar[8] = {a0.x,a0.y,a0.z,a0.w,a1.x,a1.y,a1.z,a1.w};
            float br[8] = {b0.x,b0.y,b0.z,b0.w,b1.x,b1.y,b1.z,b1.w};
            #pragma unroll
            for (int i = 0; i < 8; i++)
                #pragma unroll
                for (int j = 0; j < 8; j++)
                    acc[i][j] = fmaf(ar[i], br[j], acc[i][j]);
        }
        __syncthreads();
    }

    #pragma unroll
    for (int i = 0; i < 8; i++) {
        #pragma unroll
        for (int j = 0; j < 8; j += 4) {
            float4 v = make_float4(acc[i][j], acc[i][j+1], acc[i][j+2], acc[i][j+3]);
            *(float4*)(Cb + (size_t)(tRow + i) * N + tCol + j) = v;
        }
    }
}

// ---------------- RMSNorm + RoPE for Q (from qg buffer) ---------------------
// grid (B*S, H), block 128 (one thread per d)
__global__ __launch_bounds__(128)
void qnorm_rope_kernel(const float* __restrict__ cosb, const float* __restrict__ sinb,
                       const float* __restrict__ w) {
    int bs = blockIdx.x, h = blockIdx.y, d = threadIdx.x;
    float x = g_qg[(size_t)bs * (H_*2*D_) + h * (2*D_) + d];

    float v = x * x;
    #pragma unroll
    for (int off = 16; off; off >>= 1) v += __shfl_xor_sync(0xffffffffu, v, off);
    __shared__ float ws[4];
    int warp = d >> 5, lane = d & 31;
    if (lane == 0) ws[warp] = v;
    __syncthreads();
    float tot = ws[0] + ws[1] + ws[2] + ws[3];

    float xn = x * rsqrtf(tot * (1.f/128.f) + 1e-6f) * (1.f + w[d]);
    float o = xn;
    if (d < ROT_) {
        float xp = __shfl_xor_sync(0xffffffffu, xn, 16);
        float rot = (d < 16) ? -xp : xp;
        float c = cosb[(size_t)bs * ROT_ + d];
        float sn = sinb[(size_t)bs * ROT_ + d];
        o = xn * c + rot * sn;
    }
    int b = bs / S_, s = bs % S_;
    g_q[(((size_t)b * H_ + h) * S_ + s) * D_ + d] = o;
}

// ---------------- RMSNorm + RoPE for K, transpose V -------------------------
// grid (B*S, KV), block 128
__global__ __launch_bounds__(128)
void knorm_rope_v_kernel(const float* __restrict__ cosb, const float* __restrict__ sinb,
                         const float* __restrict__ w) {
    int bs = blockIdx.x, kv = blockIdx.y, d = threadIdx.x;
    size_t iidx = (size_t)bs * (KV_*D_) + kv * D_ + d;
    float x = g_kproj[iidx];

    float v = x * x;
    #pragma unroll
    for (int off = 16; off; off >>= 1) v += __shfl_xor_sync(0xffffffffu, v, off);
    __shared__ float ws[4];
    int warp = d >> 5, lane = d & 31;
    if (lane == 0) ws[warp] = v;
    __syncthreads();
    float tot = ws[0] + ws[1] + ws[2] + ws[3];

    float xn = x * rsqrtf(tot * (1.f/128.f) + 1e-6f) * (1.f + w[d]);
    float o = xn;
    if (d < ROT_) {
        float xp = __shfl_xor_sync(0xffffffffu, xn, 16);
        float rot = (d < 16) ? -xp : xp;
        float c = cosb[(size_t)bs * ROT_ + d];
        float sn = sinb[(size_t)bs * ROT_ + d];
        o = xn * c + rot * sn;
    }
    int b = bs / S_, s = bs % S_;
    size_t oidx = (((size_t)b * KV_ + kv) * S_ + s) * D_ + d;
    g_k[oidx] = o;
    g_v[oidx] = g_vproj[iidx];
}

// ---------------- fp32 flash attention (causal, GQA) ------------------------
// grid (B*H, S/64), block 256 (8 warps). Each warp owns 8 query rows.
#define TQ 64
#define TK 64
#define KPAD 132
#define ATTN_SMEM ((TQ*D_ + TK*KPAD + TK*D_ + TQ*TK) * 4)

__global__ __launch_bounds__(256)
void attn_kernel() {
    extern __shared__ float smem[];
    float* sQ = smem;                    // [64][128]
    float* sK = sQ + TQ * D_;            // [64][132] padded
    float* sV = sK + TK * KPAD;          // [64][128]
    float* sP = sV + TK * D_;            // [64][64]

    int bh = blockIdx.x;                 // b*H + h
    int qt = blockIdx.y;
    int b = bh / H_, h = bh % H_;
    int kv = h / GROUPS_;

    const float* qp = g_q + ((size_t)bh * S_ + (size_t)qt * TQ) * D_;
    const float* kp = g_k + ((size_t)(b * KV_ + kv) * S_) * D_;
    const float* vp = g_v + ((size_t)(b * KV_ + kv) * S_) * D_;

    int tid = threadIdx.x;
    int warp = tid >> 5, lane = tid & 31;

    // load Q tile
    for (int i = tid; i < TQ * D_ / 4; i += 256)
        ((float4*)sQ)[i] = ((const float4*)qp)[i];

    float acc[8][4];
    float m_r[8], l_r[8];
    #pragma unroll
    for (int r = 0; r < 8; r++) {
        m_r[r] = -1e30f; l_r[r] = 0.f;
        acc[r][0] = acc[r][1] = acc[r][2] = acc[r][3] = 0.f;
    }
    __syncthreads();

    int nkt = qt + 1;                   // causal: only tiles <= qt
    for (int kt = 0; kt < nkt; kt++) {
        const float* ktp = kp + (size_t)kt * TK * D_;
        const float* vtp = vp + (size_t)kt * TK * D_;
        for (int i = tid; i < TK * D_ / 4; i += 256) {
            int row = i >> 5, c4 = i & 31;
            float4 t = ((const float4*)ktp)[i];
            *(float4*)&sK[row * KPAD + (c4 << 2)] = t;
            ((float4*)sV)[i] = ((const float4*)vtp)[i];
        }
        __syncthreads();

        // scores: warp rows = warp*8..+7, cols lane and lane+32
        float s0[8], s1[8];
        #pragma unroll
        for (int r = 0; r < 8; r++) { s0[r] = 0.f; s1[r] = 0.f; }
        const float* k0p = &sK[lane * KPAD];
        const float* k1p = &sK[(lane + 32) * KPAD];
        const float* qrow = &sQ[(warp << 3) * D_];
        #pragma unroll 4
        for (int d = 0; d < D_; d++) {
            float k0 = k0p[d];
            float k1 = k1p[d];
            #pragma unroll
            for (int r = 0; r < 8; r++) {
                float qv = qrow[r * D_ + d];
                s0[r] = fmaf(qv, k0, s0[r]);
                s1[r] = fmaf(qv, k1, s1[r]);
            }
        }
        int qbase = qt * TQ + (warp << 3);
        int kbase = kt * TK;
        #pragma unroll
        for (int r = 0; r < 8; r++) {
            int qi = qbase + r;
            float a0 = s0[r] * SCALE_ + ((kbase + lane)      > qi ? NEG_ : 0.f);
            float a1 = s1[r] * SCALE_ + ((kbase + lane + 32) > qi ? NEG_ : 0.f);
            float mx = fmaxf(a0, a1);
            #pragma unroll
            for (int off = 16; off; off >>= 1)
                mx = fmaxf(mx, __shfl_xor_sync(0xffffffffu, mx, off));
            float nm = fmaxf(m_r[r], mx);
            float p0 = __expf(a0 - nm);
            float p1 = __expf(a1 - nm);
            float sum = p0 + p1;
            #pragma unroll
            for (int off = 16; off; off >>= 1)
                sum += __shfl_xor_sync(0xffffffffu, sum, off);
            float corr = __expf(m_r[r] - nm);
            l_r[r] = l_r[r] * corr + sum;
            m_r[r] = nm;
            acc[r][0] *= corr; acc[r][1] *= corr;
            acc[r][2] *= corr; acc[r][3] *= corr;
            sP[((warp << 3) + r) * TK + lane]      = p0;
            sP[((warp << 3) + r) * TK + lane + 32] = p1;
        }
        __syncwarp();

        // PV: acc[r][0..3] += P[row][j] * V[j][lane*4 .. +3]
        #pragma unroll 2
        for (int j = 0; j < TK; j++) {
            float4 v4 = *(const float4*)&sV[j * D_ + (lane << 2)];
            #pragma unroll
            for (int r = 0; r < 8; r++) {
                float p = sP[((warp << 3) + r) * TK + j];
                acc[r][0] = fmaf(p, v4.x, acc[r][0]);
                acc[r][1] = fmaf(p, v4.y, acc[r][1]);
                acc[r][2] = fmaf(p, v4.z, acc[r][2]);
                acc[r][3] = fmaf(p, v4.w, acc[r][3]);
            }
        }
        __syncthreads();
    }

    #pragma unroll
    for (int r = 0; r < 8; r++) {
        float inv = 1.f / l_r[r];
        float4 o4 = make_float4(acc[r][0] * inv, acc[r][1] * inv,
                                acc[r][2] * inv, acc[r][3] * inv);
        size_t row = (size_t)bh * S_ + (size_t)qt * TQ + (warp << 3) + r;
        *(float4*)&g_attn[row * D_ + (lane << 2)] = o4;
    }
}

// ---------------- gate: gated = attn * sigmoid(gate) ------------------------
__global__ __launch_bounds__(256)
void gate_kernel() {
    size_t idx = (size_t)blockIdx.x * 256 + threadIdx.x;   // over B*S*H*D
    int bs = (int)(idx >> 11);          // / 2048
    int c  = (int)(idx & 2047);
    int h = c >> 7, d = c & 127;
    float g = g_qg[(size_t)bs * (H_*2*D_) + h * (2*D_) + D_ + d];
    int b = bs / S_, s = bs % S_;
    float a = g_attn[(((size_t)b * H_ + h) * S_ + s) * D_ + d];
    g_gated[idx] = a * (1.f / (1.f + __expf(-g)));
}

// ---------------- launch ----------------------------------------------------
extern "C" void kernel_launch(void* const* d_in, const int* in_sizes, int n_in,
                              void* d_out, int out_size) {
    const float* hidden = (const float*)d_in[0];   // [B,S,HID]
    const float* cosb   = (const float*)d_in[1];   // [B,S,ROT]
    const float* sinb   = (const float*)d_in[2];   // [B,S,ROT]
    // d_in[3] = attention_mask (pure causal; computed arithmetically)
    const float* wq     = (const float*)d_in[4];   // [HID, H*2D]
    const float* wk     = (const float*)d_in[5];   // [HID, KV*D]
    const float* wv     = (const float*)d_in[6];   // [HID, KV*D]
    const float* wo     = (const float*)d_in[7];   // [H*D, HID]
    const float* qnw    = (const float*)d_in[8];   // [D]
    const float* knw    = (const float*)d_in[9];   // [D]
    float* out = (float*)d_out;

    float *qg, *kproj, *vproj, *gated;
    cudaGetSymbolAddress((void**)&qg,    g_qg);
    cudaGetSymbolAddress((void**)&kproj, g_kproj);
    cudaGetSymbolAddress((void**)&vproj, g_vproj);
    cudaGetSymbolAddress((void**)&gated, g_gated);

    cudaFuncSetAttribute(attn_kernel,
                         cudaFuncAttributeMaxDynamicSharedMemorySize, ATTN_SMEM);

    const int M = B_ * S_;   // 8192

    // projections
    sgemm128<<<dim3((H_*2*D_)/128, M/128), 256>>>(hidden, wq, qg,    M, H_*2*D_, HID_);
    sgemm128<<<dim3((KV_*D_)/128,  M/128), 256>>>(hidden, wk, kproj, M, KV_*D_,  HID_);
    sgemm128<<<dim3((KV_*D_)/128,  M/128), 256>>>(hidden, wv, vproj, M, KV_*D_,  HID_);

    // norms + rope + transpose
    qnorm_rope_kernel  <<<dim3(M, H_),  128>>>(cosb, sinb, qnw);
    knorm_rope_v_kernel<<<dim3(M, KV_), 128>>>(cosb, sinb, knw);

    // attention
    attn_kernel<<<dim3(B_*H_, S_/TQ), 256, ATTN_SMEM>>>();

    // gate + output projection
    gate_kernel<<<(B_*S_*H_*D_)/256, 256>>>();
    sgemm128<<<dim3(HID_/128, M/128), 256>>>(gated, wo, out, M, HID_, H_*D_);
}

// round 2
// speedup vs baseline: 1.7099x; 1.7099x over previous
#include <cuda_runtime.h>
#include <cuda_bf16.h>
#include <math.h>
#include <stdint.h>

#define B_ 4
#define S_ 2048
#define HID_ 2048
#define H_ 16
#define KV_ 4
#define D_ 128
#define ROT_ 32
#define GROUPS_ (H_/KV_)
#define NEG_ (-1000000000.0f)
#define SCALE_ 0.08838834764831845f   // D^-0.5

// ---------------- scratch (device globals; no allocations allowed) ----------
__device__ float g_qg   [(size_t)B_*S_*H_*2*D_];   // [B*S, H*2D]  q|gate
__device__ float g_kproj[(size_t)B_*S_*KV_*D_];    // [B*S, KV*D]
__device__ float g_vproj[(size_t)B_*S_*KV_*D_];    // [B*S, KV*D]
__device__ float g_q    [(size_t)B_*H_*S_*D_];     // [B,H,S,D]
__device__ float g_k    [(size_t)B_*KV_*S_*D_];    // [B,KV,S,D]
__device__ float g_v    [(size_t)B_*KV_*S_*D_];    // [B,KV,S,D]
__device__ float g_attn [(size_t)B_*H_*S_*D_];     // [B,H,S,D]
__device__ float g_gated[(size_t)B_*S_*H_*D_];     // [B*S, H*D]

// ---------------- mma helpers ------------------------------------------------
__device__ __forceinline__ uint32_t smem_u32(const void* p) {
    return (uint32_t)__cvta_generic_to_shared(p);
}
__device__ __forceinline__ void ldm_x4(uint32_t* r, uint32_t addr) {
    asm volatile("ldmatrix.sync.aligned.m8n8.x4.shared.b16 {%0,%1,%2,%3}, [%4];\n"
                 : "=r"(r[0]), "=r"(r[1]), "=r"(r[2]), "=r"(r[3]) : "r"(addr));
}
__device__ __forceinline__ void ldm_x4_t(uint32_t* r, uint32_t addr) {
    asm volatile("ldmatrix.sync.aligned.m8n8.x4.trans.shared.b16 {%0,%1,%2,%3}, [%4];\n"
                 : "=r"(r[0]), "=r"(r[1]), "=r"(r[2]), "=r"(r[3]) : "r"(addr));
}
__device__ __forceinline__ void mma_bf16(float* c, const uint32_t* a,
                                         uint32_t b0, uint32_t b1) {
    asm volatile(
        "mma.sync.aligned.m16n8k16.row.col.f32.bf16.bf16.f32 "
        "{%0,%1,%2,%3}, {%4,%5,%6,%7}, {%8,%9}, {%0,%1,%2,%3};\n"
        : "+f"(c[0]), "+f"(c[1]), "+f"(c[2]), "+f"(c[3])
        : "r"(a[0]), "r"(a[1]), "r"(a[2]), "r"(a[3]), "r"(b0), "r"(b1));
}

// ---------------- bf16x3 tensor-core GEMM -----------------------------------
// C[M,N] = A[M,K] @ B[K,N], fp32 in/out, bf16 hi/lo split (3 mmas) for accuracy.
// Block tile 128x128x32, 256 threads (8 warps, 2x4), warp tile 64x32.
#define BM 128
#define BN 128
#define BKG 32
#define ASTR (BKG + 8)    // bf16 elements per A smem row (40)
#define BSTR (BN + 8)     // bf16 elements per B smem row (136)

__global__ __launch_bounds__(256)
void gemm_bf16x3(const float* __restrict__ A, const float* __restrict__ B,
                 float* __restrict__ C, int M, int N, int K) {
    __shared__ __nv_bfloat16 sAhi[BM * ASTR];
    __shared__ __nv_bfloat16 sAlo[BM * ASTR];
    __shared__ __nv_bfloat16 sBhi[BKG * BSTR];
    __shared__ __nv_bfloat16 sBlo[BKG * BSTR];

    int tid = threadIdx.x;
    int warp = tid >> 5, lane = tid & 31;
    int wm = (warp >> 2) * 64;     // warp row offset in tile (0 or 64)
    int wn = (warp & 3) * 32;      // warp col offset (0..96)

    const float* Ab = A + (size_t)blockIdx.y * BM * K;
    const float* Bb = B + (size_t)blockIdx.x * BN;

    float acc[4][4][4];
    #pragma unroll
    for (int mt = 0; mt < 4; mt++)
        #pragma unroll
        for (int nt = 0; nt < 4; nt++)
            #pragma unroll
            for (int i = 0; i < 4; i++) acc[mt][nt][i] = 0.f;

    int aRow = tid >> 3;            // 0..31
    int aCol = (tid & 7) << 2;      // 0..28 step 4
    int bRow = tid >> 5;            // 0..7
    int bCol = (tid & 31) << 2;     // 0..124 step 4

    for (int k0 = 0; k0 < K; k0 += BKG) {
        // ---- load + split A tile [128 x 32]
        #pragma unroll
        for (int i = 0; i < 4; i++) {
            int r = aRow + i * 32;
            float4 v = *(const float4*)(Ab + (size_t)r * K + k0 + aCol);
            int base = r * ASTR + aCol;
            float xs[4] = {v.x, v.y, v.z, v.w};
            #pragma unroll
            for (int j = 0; j < 4; j++) {
                __nv_bfloat16 h = __float2bfloat16(xs[j]);
                sAhi[base + j] = h;
                sAlo[base + j] = __float2bfloat16(xs[j] - __bfloat162float(h));
            }
        }
        // ---- load + split B tile [32 x 128]
        #pragma unroll
        for (int i = 0; i < 4; i++) {
            int r = bRow + i * 8;
            float4 v = *(const float4*)(Bb + (size_t)(k0 + r) * N + bCol);
            int base = r * BSTR + bCol;
            float xs[4] = {v.x, v.y, v.z, v.w};
            #pragma unroll
            for (int j = 0; j < 4; j++) {
                __nv_bfloat16 h = __float2bfloat16(xs[j]);
                sBhi[base + j] = h;
                sBlo[base + j] = __float2bfloat16(xs[j] - __bfloat162float(h));
            }
        }
        __syncthreads();

        #pragma unroll
        for (int ks = 0; ks < 2; ks++) {
            int kk = ks * 16;
            uint32_t ahi[4][4], alo[4][4];
            #pragma unroll
            for (int mt = 0; mt < 4; mt++) {
                int row = wm + mt * 16 + (lane & 15);
                int col = kk + ((lane >> 4) << 3);
                ldm_x4(ahi[mt], smem_u32(&sAhi[row * ASTR + col]));
                ldm_x4(alo[mt], smem_u32(&sAlo[row * ASTR + col]));
            }
            uint32_t bhi[2][4], blo[2][4];
            #pragma unroll
            for (int nc = 0; nc < 2; nc++) {
                int row = kk + (lane & 15);
                int col = wn + nc * 16 + ((lane >> 4) << 3);
                ldm_x4_t(bhi[nc], smem_u32(&sBhi[row * BSTR + col]));
                ldm_x4_t(blo[nc], smem_u32(&sBlo[row * BSTR + col]));
            }
            #pragma unroll
            for (int mt = 0; mt < 4; mt++) {
                #pragma unroll
                for (int nt = 0; nt < 4; nt++) {
                    int nc = nt >> 1, off = (nt & 1) << 1;
                    mma_bf16(acc[mt][nt], ahi[mt], bhi[nc][off], bhi[nc][off + 1]);
                    mma_bf16(acc[mt][nt], ahi[mt], blo[nc][off], blo[nc][off + 1]);
                    mma_bf16(acc[mt][nt], alo[mt], bhi[nc][off], bhi[nc][off + 1]);
                }
            }
        }
        __syncthreads();
    }

    // ---- epilogue
    float* Cb = C + (size_t)blockIdx.y * BM * N + (size_t)blockIdx.x * BN;
    #pragma unroll
    for (int mt = 0; mt < 4; mt++) {
        #pragma unroll
        for (int nt = 0; nt < 4; nt++) {
            int r = wm + mt * 16 + (lane >> 2);
            int c = wn + nt * 8 + ((lane & 3) << 1);
            float2 v0 = make_float2(acc[mt][nt][0], acc[mt][nt][1]);
            float2 v1 = make_float2(acc[mt][nt][2], acc[mt][nt][3]);
            *(float2*)&Cb[(size_t)r * N + c] = v0;
            *(float2*)&Cb[(size_t)(r + 8) * N + c] = v1;
        }
    }
}

// ---------------- RMSNorm + RoPE for Q (from qg buffer) ---------------------
__global__ __launch_bounds__(128)
void qnorm_rope_kernel(const float* __restrict__ cosb, const float* __restrict__ sinb,
                       const float* __restrict__ w) {
    int bs = blockIdx.x, h = blockIdx.y, d = threadIdx.x;
    float x = g_qg[(size_t)bs * (H_*2*D_) + h * (2*D_) + d];

    float v = x * x;
    #pragma unroll
    for (int off = 16; off; off >>= 1) v += __shfl_xor_sync(0xffffffffu, v, off);
    __shared__ float ws[4];
    int warp = d >> 5, lane = d & 31;
    if (lane == 0) ws[warp] = v;
    __syncthreads();
    float tot = ws[0] + ws[1] + ws[2] + ws[3];

    float xn = x * rsqrtf(tot * (1.f/128.f) + 1e-6f) * (1.f + w[d]);
    float o = xn;
    if (d < ROT_) {
        float xp = __shfl_xor_sync(0xffffffffu, xn, 16);
        float rot = (d < 16) ? -xp : xp;
        float c = cosb[(size_t)bs * ROT_ + d];
        float sn = sinb[(size_t)bs * ROT_ + d];
        o = xn * c + rot * sn;
    }
    int b = bs / S_, s = bs % S_;
    g_q[(((size_t)b * H_ + h) * S_ + s) * D_ + d] = o;
}

// ---------------- RMSNorm + RoPE for K, transpose V -------------------------
__global__ __launch_bounds__(128)
void knorm_rope_v_kernel(const float* __restrict__ cosb, const float* __restrict__ sinb,
                         const float* __restrict__ w) {
    int bs = blockIdx.x, kv = blockIdx.y, d = threadIdx.x;
    size_t iidx = (size_t)bs * (KV_*D_) + kv * D_ + d;
    float x = g_kproj[iidx];

    float v = x * x;
    #pragma unroll
    for (int off = 16; off; off >>= 1) v += __shfl_xor_sync(0xffffffffu, v, off);
    __shared__ float ws[4];
    int warp = d >> 5, lane = d & 31;
    if (lane == 0) ws[warp] = v;
    __syncthreads();
    float tot = ws[0] + ws[1] + ws[2] + ws[3];

    float xn = x * rsqrtf(tot * (1.f/128.f) + 1e-6f) * (1.f + w[d]);
    float o = xn;
    if (d < ROT_) {
        float xp = __shfl_xor_sync(0xffffffffu, xn, 16);
        float rot = (d < 16) ? -xp : xp;
        float c = cosb[(size_t)bs * ROT_ + d];
        float sn = sinb[(size_t)bs * ROT_ + d];
        o = xn * c + rot * sn;
    }
    int b = bs / S_, s = bs % S_;
    size_t oidx = (((size_t)b * KV_ + kv) * S_ + s) * D_ + d;
    g_k[oidx] = o;
    g_v[oidx] = g_vproj[iidx];
}

// ---------------- fp32 flash attention (causal, GQA) ------------------------
#define TQ 64
#define TK 64
#define KPAD 132
#define ATTN_SMEM ((TQ*D_ + TK*KPAD + TK*D_ + TQ*TK) * 4)

__global__ __launch_bounds__(256)
void attn_kernel() {
    extern __shared__ float smem[];
    float* sQ = smem;                    // [64][128]
    float* sK = sQ + TQ * D_;            // [64][132] padded
    float* sV = sK + TK * KPAD;          // [64][128]
    float* sP = sV + TK * D_;            // [64][64]

    int bh = blockIdx.x;                 // b*H + h
    int qt = blockIdx.y;
    int b = bh / H_, h = bh % H_;
    int kv = h / GROUPS_;

    const float* qp = g_q + ((size_t)bh * S_ + (size_t)qt * TQ) * D_;
    const float* kp = g_k + ((size_t)(b * KV_ + kv) * S_) * D_;
    const float* vp = g_v + ((size_t)(b * KV_ + kv) * S_) * D_;

    int tid = threadIdx.x;
    int warp = tid >> 5, lane = tid & 31;

    for (int i = tid; i < TQ * D_ / 4; i += 256)
        ((float4*)sQ)[i] = ((const float4*)qp)[i];

    float acc[8][4];
    float m_r[8], l_r[8];
    #pragma unroll
    for (int r = 0; r < 8; r++) {
        m_r[r] = -1e30f; l_r[r] = 0.f;
        acc[r][0] = acc[r][1] = acc[r][2] = acc[r][3] = 0.f;
    }
    __syncthreads();

    int nkt = qt + 1;
    for (int kt = 0; kt < nkt; kt++) {
        const float* ktp = kp + (size_t)kt * TK * D_;
        const float* vtp = vp + (size_t)kt * TK * D_;
        for (int i = tid; i < TK * D_ / 4; i += 256) {
            int row = i >> 5, c4 = i & 31;
            float4 t = ((const float4*)ktp)[i];
            *(float4*)&sK[row * KPAD + (c4 << 2)] = t;
            ((float4*)sV)[i] = ((const float4*)vtp)[i];
        }
        __syncthreads();

        float s0[8], s1[8];
        #pragma unroll
        for (int r = 0; r < 8; r++) { s0[r] = 0.f; s1[r] = 0.f; }
        const float* k0p = &sK[lane * KPAD];
        const float* k1p = &sK[(lane + 32) * KPAD];
        const float* qrow = &sQ[(warp << 3) * D_];
        #pragma unroll 4
        for (int d = 0; d < D_; d++) {
            float k0 = k0p[d];
            float k1 = k1p[d];
            #pragma unroll
            for (int r = 0; r < 8; r++) {
                float qv = qrow[r * D_ + d];
                s0[r] = fmaf(qv, k0, s0[r]);
                s1[r] = fmaf(qv, k1, s1[r]);
            }
        }
        int qbase = qt * TQ + (warp << 3);
        int kbase = kt * TK;
        #pragma unroll
        for (int r = 0; r < 8; r++) {
            int qi = qbase + r;
            float a0 = s0[r] * SCALE_ + ((kbase + lane)      > qi ? NEG_ : 0.f);
            float a1 = s1[r] * SCALE_ + ((kbase + lane + 32) > qi ? NEG_ : 0.f);
            float mx = fmaxf(a0, a1);
            #pragma unroll
            for (int off = 16; off; off >>= 1)
                mx = fmaxf(mx, __shfl_xor_sync(0xffffffffu, mx, off));
            float nm = fmaxf(m_r[r], mx);
            float p0 = __expf(a0 - nm);
            float p1 = __expf(a1 - nm);
            float sum = p0 + p1;
            #pragma unroll
            for (int off = 16; off; off >>= 1)
                sum += __shfl_xor_sync(0xffffffffu, sum, off);
            float corr = __expf(m_r[r] - nm);
            l_r[r] = l_r[r] * corr + sum;
            m_r[r] = nm;
            acc[r][0] *= corr; acc[r][1] *= corr;
            acc[r][2] *= corr; acc[r][3] *= corr;
            sP[((warp << 3) + r) * TK + lane]      = p0;
            sP[((warp << 3) + r) * TK + lane + 32] = p1;
        }
        __syncwarp();

        #pragma unroll 2
        for (int j = 0; j < TK; j++) {
            float4 v4 = *(const float4*)&sV[j * D_ + (lane << 2)];
            #pragma unroll
            for (int r = 0; r < 8; r++) {
                float p = sP[((warp << 3) + r) * TK + j];
                acc[r][0] = fmaf(p, v4.x, acc[r][0]);
                acc[r][1] = fmaf(p, v4.y, acc[r][1]);
                acc[r][2] = fmaf(p, v4.z, acc[r][2]);
                acc[r][3] = fmaf(p, v4.w, acc[r][3]);
            }
        }
        __syncthreads();
    }

    #pragma unroll
    for (int r = 0; r < 8; r++) {
        float inv = 1.f / l_r[r];
        float4 o4 = make_float4(acc[r][0] * inv, acc[r][1] * inv,
                                acc[r][2] * inv, acc[r][3] * inv);
        size_t row = (size_t)bh * S_ + (size_t)qt * TQ + (warp << 3) + r;
        *(float4*)&g_attn[row * D_ + (lane << 2)] = o4;
    }
}

// ---------------- gate: gated = attn * sigmoid(gate) ------------------------
__global__ __launch_bounds__(256)
void gate_kernel() {
    size_t idx = (size_t)blockIdx.x * 256 + threadIdx.x;
    int bs = (int)(idx >> 11);
    int c  = (int)(idx & 2047);
    int h = c >> 7, d = c & 127;
    float g = g_qg[(size_t)bs * (H_*2*D_) + h * (2*D_) + D_ + d];
    int b = bs / S_, s = bs % S_;
    float a = g_attn[(((size_t)b * H_ + h) * S_ + s) * D_ + d];
    g_gated[idx] = a * (1.f / (1.f + __expf(-g)));
}

// ---------------- launch ----------------------------------------------------
extern "C" void kernel_launch(void* const* d_in, const int* in_sizes, int n_in,
                              void* d_out, int out_size) {
    const float* hidden = (const float*)d_in[0];   // [B,S,HID]
    const float* cosb   = (const float*)d_in[1];   // [B,S,ROT]
    const float* sinb   = (const float*)d_in[2];   // [B,S,ROT]
    // d_in[3] = attention_mask (pure causal; computed arithmetically)
    const float* wq     = (const float*)d_in[4];   // [HID, H*2D]
    const float* wk     = (const float*)d_in[5];   // [HID, KV*D]
    const float* wv     = (const float*)d_in[6];   // [HID, KV*D]
    const float* wo     = (const float*)d_in[7];   // [H*D, HID]
    const float* qnw    = (const float*)d_in[8];   // [D]
    const float* knw    = (const float*)d_in[9];   // [D]
    float* out = (float*)d_out;

    float *qg, *kproj, *vproj, *gated;
    cudaGetSymbolAddress((void**)&qg,    g_qg);
    cudaGetSymbolAddress((void**)&kproj, g_kproj);
    cudaGetSymbolAddress((void**)&vproj, g_vproj);
    cudaGetSymbolAddress((void**)&gated, g_gated);

    cudaFuncSetAttribute(attn_kernel,
                         cudaFuncAttributeMaxDynamicSharedMemorySize, ATTN_SMEM);

    const int M = B_ * S_;   // 8192

    // projections (tensor-core bf16x3)
    gemm_bf16x3<<<dim3((H_*2*D_)/BN, M/BM), 256>>>(hidden, wq, qg,    M, H_*2*D_, HID_);
    gemm_bf16x3<<<dim3((KV_*D_)/BN,  M/BM), 256>>>(hidden, wk, kproj, M, KV_*D_,  HID_);
    gemm_bf16x3<<<dim3((KV_*D_)/BN,  M/BM), 256>>>(hidden, wv, vproj, M, KV_*D_,  HID_);

    // norms + rope + transpose
    qnorm_rope_kernel  <<<dim3(M, H_),  128>>>(cosb, sinb, qnw);
    knorm_rope_v_kernel<<<dim3(M, KV_), 128>>>(cosb, sinb, knw);

    // attention
    attn_kernel<<<dim3(B_*H_, S_/TQ), 256, ATTN_SMEM>>>();

    // gate + output projection
    gate_kernel<<<(B_*S_*H_*D_)/256, 256>>>();
    gemm_bf16x3<<<dim3(HID_/BN, M/BM), 256>>>(gated, wo, out, M, HID_, H_*D_);
}

// round 4
// speedup vs baseline: 2.3111x; 1.3516x over previous
#include <cuda_runtime.h>
#include <cuda_bf16.h>
#include <math.h>
#include <stdint.h>

#define B_ 4
#define S_ 2048
#define HID_ 2048
#define H_ 16
#define KV_ 4
#define D_ 128
#define ROT_ 32
#define GROUPS_ (H_/KV_)
#define NEG_ (-1000000000.0f)
#define SCALE_ 0.08838834764831845f   // D^-0.5

// ---------------- scratch (device globals; no allocations allowed) ----------
__device__ float g_qg   [(size_t)B_*S_*H_*2*D_];   // [B*S, H*2D]  q|gate
__device__ float g_kproj[(size_t)B_*S_*KV_*D_];    // [B*S, KV*D]
__device__ float g_vproj[(size_t)B_*S_*KV_*D_];    // [B*S, KV*D]
__device__ float g_gated[(size_t)B_*S_*H_*D_];     // [B*S, H*D]
__device__ __nv_bfloat16 g_qhi[(size_t)B_*H_*S_*D_];
__device__ __nv_bfloat16 g_qlo[(size_t)B_*H_*S_*D_];
__device__ __nv_bfloat16 g_khi[(size_t)B_*KV_*S_*D_];
__device__ __nv_bfloat16 g_klo[(size_t)B_*KV_*S_*D_];
__device__ __nv_bfloat16 g_vhi[(size_t)B_*KV_*S_*D_];
__device__ __nv_bfloat16 g_vlo[(size_t)B_*KV_*S_*D_];

// ---------------- mma helpers ------------------------------------------------
__device__ __forceinline__ uint32_t smem_u32(const void* p) {
    return (uint32_t)__cvta_generic_to_shared(p);
}
__device__ __forceinline__ void ldm_x4(uint32_t* r, uint32_t addr) {
    asm volatile("ldmatrix.sync.aligned.m8n8.x4.shared.b16 {%0,%1,%2,%3}, [%4];\n"
                 : "=r"(r[0]), "=r"(r[1]), "=r"(r[2]), "=r"(r[3]) : "r"(addr));
}
__device__ __forceinline__ void ldm_x4_t(uint32_t* r, uint32_t addr) {
    asm volatile("ldmatrix.sync.aligned.m8n8.x4.trans.shared.b16 {%0,%1,%2,%3}, [%4];\n"
                 : "=r"(r[0]), "=r"(r[1]), "=r"(r[2]), "=r"(r[3]) : "r"(addr));
}
__device__ __forceinline__ void mma_bf16(float* c, const uint32_t* a,
                                         uint32_t b0, uint32_t b1) {
    asm volatile(
        "mma.sync.aligned.m16n8k16.row.col.f32.bf16.bf16.f32 "
        "{%0,%1,%2,%3}, {%4,%5,%6,%7}, {%8,%9}, {%0,%1,%2,%3};\n"
        : "+f"(c[0]), "+f"(c[1]), "+f"(c[2]), "+f"(c[3])
        : "r"(a[0]), "r"(a[1]), "r"(a[2]), "r"(a[3]), "r"(b0), "r"(b1));
}
__device__ __forceinline__ void mma_bf16_s(float* c, uint32_t a0, uint32_t a1,
                                           uint32_t a2, uint32_t a3,
                                           uint32_t b0, uint32_t b1) {
    asm volatile(
        "mma.sync.aligned.m16n8k16.row.col.f32.bf16.bf16.f32 "
        "{%0,%1,%2,%3}, {%4,%5,%6,%7}, {%8,%9}, {%0,%1,%2,%3};\n"
        : "+f"(c[0]), "+f"(c[1]), "+f"(c[2]), "+f"(c[3])
        : "r"(a0), "r"(a1), "r"(a2), "r"(a3), "r"(b0), "r"(b1));
}
__device__ __forceinline__ uint32_t bf2_u32(__nv_bfloat162 v) {
    return *reinterpret_cast<uint32_t*>(&v);
}

// ---------------- bf16x3 tensor-core GEMM -----------------------------------
#define BM 128
#define BN 128
#define BKG 32
#define ASTR (BKG + 8)
#define BSTR (BN + 8)

__global__ __launch_bounds__(256)
void gemm_bf16x3(const float* __restrict__ A, const float* __restrict__ B,
                 float* __restrict__ C, int M, int N, int K) {
    __shared__ __nv_bfloat16 sAhi[BM * ASTR];
    __shared__ __nv_bfloat16 sAlo[BM * ASTR];
    __shared__ __nv_bfloat16 sBhi[BKG * BSTR];
    __shared__ __nv_bfloat16 sBlo[BKG * BSTR];

    int tid = threadIdx.x;
    int warp = tid >> 5, lane = tid & 31;
    int wm = (warp >> 2) * 64;
    int wn = (warp & 3) * 32;

    const float* Ab = A + (size_t)blockIdx.y * BM * K;
    const float* Bb = B + (size_t)blockIdx.x * BN;

    float acc[4][4][4];
    #pragma unroll
    for (int mt = 0; mt < 4; mt++)
        #pragma unroll
        for (int nt = 0; nt < 4; nt++)
            #pragma unroll
            for (int i = 0; i < 4; i++) acc[mt][nt][i] = 0.f;

    int aRow = tid >> 3;
    int aCol = (tid & 7) << 2;
    int bRow = tid >> 5;
    int bCol = (tid & 31) << 2;

    for (int k0 = 0; k0 < K; k0 += BKG) {
        #pragma unroll
        for (int i = 0; i < 4; i++) {
            int r = aRow + i * 32;
            float4 v = *(const float4*)(Ab + (size_t)r * K + k0 + aCol);
            int base = r * ASTR + aCol;
            float xs[4] = {v.x, v.y, v.z, v.w};
            #pragma unroll
            for (int j = 0; j < 4; j++) {
                __nv_bfloat16 h = __float2bfloat16(xs[j]);
                sAhi[base + j] = h;
                sAlo[base + j] = __float2bfloat16(xs[j] - __bfloat162float(h));
            }
        }
        #pragma unroll
        for (int i = 0; i < 4; i++) {
            int r = bRow + i * 8;
            float4 v = *(const float4*)(Bb + (size_t)(k0 + r) * N + bCol);
            int base = r * BSTR + bCol;
            float xs[4] = {v.x, v.y, v.z, v.w};
            #pragma unroll
            for (int j = 0; j < 4; j++) {
                __nv_bfloat16 h = __float2bfloat16(xs[j]);
                sBhi[base + j] = h;
                sBlo[base + j] = __float2bfloat16(xs[j] - __bfloat162float(h));
            }
        }
        __syncthreads();

        #pragma unroll
        for (int ks = 0; ks < 2; ks++) {
            int kk = ks * 16;
            uint32_t ahi[4][4], alo[4][4];
            #pragma unroll
            for (int mt = 0; mt < 4; mt++) {
                int row = wm + mt * 16 + (lane & 15);
                int col = kk + ((lane >> 4) << 3);
                ldm_x4(ahi[mt], smem_u32(&sAhi[row * ASTR + col]));
                ldm_x4(alo[mt], smem_u32(&sAlo[row * ASTR + col]));
            }
            uint32_t bhi[2][4], blo[2][4];
            #pragma unroll
            for (int nc = 0; nc < 2; nc++) {
                int row = kk + (lane & 15);
                int col = wn + nc * 16 + ((lane >> 4) << 3);
                ldm_x4_t(bhi[nc], smem_u32(&sBhi[row * BSTR + col]));
                ldm_x4_t(blo[nc], smem_u32(&sBlo[row * BSTR + col]));
            }
            #pragma unroll
            for (int mt = 0; mt < 4; mt++) {
                #pragma unroll
                for (int nt = 0; nt < 4; nt++) {
                    int nc = nt >> 1, off = (nt & 1) << 1;
                    mma_bf16(acc[mt][nt], ahi[mt], bhi[nc][off], bhi[nc][off + 1]);
                    mma_bf16(acc[mt][nt], ahi[mt], blo[nc][off], blo[nc][off + 1]);
                    mma_bf16(acc[mt][nt], alo[mt], bhi[nc][off], bhi[nc][off + 1]);
                }
            }
        }
        __syncthreads();
    }

    float* Cb = C + (size_t)blockIdx.y * BM * N + (size_t)blockIdx.x * BN;
    #pragma unroll
    for (int mt = 0; mt < 4; mt++) {
        #pragma unroll
        for (int nt = 0; nt < 4; nt++) {
            int r = wm + mt * 16 + (lane >> 2);
            int c = wn + nt * 8 + ((lane & 3) << 1);
            *(float2*)&Cb[(size_t)r * N + c] = make_float2(acc[mt][nt][0], acc[mt][nt][1]);
            *(float2*)&Cb[(size_t)(r + 8) * N + c] = make_float2(acc[mt][nt][2], acc[mt][nt][3]);
        }
    }
}

// ---------------- RMSNorm + RoPE for Q -> bf16 hi/lo ------------------------
__global__ __launch_bounds__(128)
void qnorm_rope_kernel(const float* __restrict__ cosb, const float* __restrict__ sinb,
                       const float* __restrict__ w) {
    int bs = blockIdx.x, h = blockIdx.y, d = threadIdx.x;
    float x = g_qg[(size_t)bs * (H_*2*D_) + h * (2*D_) + d];

    float v = x * x;
    #pragma unroll
    for (int off = 16; off; off >>= 1) v += __shfl_xor_sync(0xffffffffu, v, off);
    __shared__ float ws[4];
    int warp = d >> 5, lane = d & 31;
    if (lane == 0) ws[warp] = v;
    __syncthreads();
    float tot = ws[0] + ws[1] + ws[2] + ws[3];

    float xn = x * rsqrtf(tot * (1.f/128.f) + 1e-6f) * (1.f + w[d]);
    float o = xn;
    if (d < ROT_) {
        float xp = __shfl_xor_sync(0xffffffffu, xn, 16);
        float rot = (d < 16) ? -xp : xp;
        float c = cosb[(size_t)bs * ROT_ + d];
        float sn = sinb[(size_t)bs * ROT_ + d];
        o = xn * c + rot * sn;
    }
    int b = bs / S_, s = bs % S_;
    size_t idx = (((size_t)b * H_ + h) * S_ + s) * D_ + d;
    __nv_bfloat16 hi = __float2bfloat16(o);
    g_qhi[idx] = hi;
    g_qlo[idx] = __float2bfloat16(o - __bfloat162float(hi));
}

// ---------------- RMSNorm + RoPE for K, V -> bf16 hi/lo ---------------------
__global__ __launch_bounds__(128)
void knorm_rope_v_kernel(const float* __restrict__ cosb, const float* __restrict__ sinb,
                         const float* __restrict__ w) {
    int bs = blockIdx.x, kv = blockIdx.y, d = threadIdx.x;
    size_t iidx = (size_t)bs * (KV_*D_) + kv * D_ + d;
    float x = g_kproj[iidx];

    float v = x * x;
    #pragma unroll
    for (int off = 16; off; off >>= 1) v += __shfl_xor_sync(0xffffffffu, v, off);
    __shared__ float ws[4];
    int warp = d >> 5, lane = d & 31;
    if (lane == 0) ws[warp] = v;
    __syncthreads();
    float tot = ws[0] + ws[1] + ws[2] + ws[3];

    float xn = x * rsqrtf(tot * (1.f/128.f) + 1e-6f) * (1.f + w[d]);
    float o = xn;
    if (d < ROT_) {
        float xp = __shfl_xor_sync(0xffffffffu, xn, 16);
        float rot = (d < 16) ? -xp : xp;
        float c = cosb[(size_t)bs * ROT_ + d];
        float sn = sinb[(size_t)bs * ROT_ + d];
        o = xn * c + rot * sn;
    }
    int b = bs / S_, s = bs % S_;
    size_t oidx = (((size_t)b * KV_ + kv) * S_ + s) * D_ + d;
    __nv_bfloat16 khi = __float2bfloat16(o);
    g_khi[oidx] = khi;
    g_klo[oidx] = __float2bfloat16(o - __bfloat162float(khi));
    float vv = g_vproj[iidx];
    __nv_bfloat16 vhi = __float2bfloat16(vv);
    g_vhi[oidx] = vhi;
    g_vlo[oidx] = __float2bfloat16(vv - __bfloat162float(vhi));
}

// ---------------- tensor-core flash attention (causal, GQA) -----------------
// TQ=128 (8 warps x m16), TK=64. bf16 hi/lo compensated QK and PV.
// Epilogue fuses sigmoid gating; writes g_gated directly.
#define AQS 136
#define ATT_SMEM ((2*128*AQS + 4*64*AQS) * 2)   // bytes (bf16)

__global__ __launch_bounds__(256)
void attn_mma_kernel() {
    extern __shared__ __align__(16) __nv_bfloat16 smA[];
    __nv_bfloat16* sQh = smA;
    __nv_bfloat16* sQl = sQh + 128 * AQS;
    __nv_bfloat16* sKh = sQl + 128 * AQS;
    __nv_bfloat16* sKl = sKh + 64 * AQS;
    __nv_bfloat16* sVh = sKl + 64 * AQS;
    __nv_bfloat16* sVl = sVh + 64 * AQS;

    int tid = threadIdx.x, warp = tid >> 5, lane = tid & 31;
    int bh = blockIdx.x, qt = blockIdx.y;
    int b = bh >> 4, h = bh & 15, kvh = h >> 2;

    size_t qoff = ((size_t)bh * S_ + (size_t)qt * 128) * D_;
    size_t kvoff = ((size_t)(b * KV_ + kvh) * S_) * D_;

    // load Q tile (hi/lo)
    for (int i = tid; i < 2048; i += 256) {
        int r = i >> 4, c = (i & 15) << 3;
        *(uint4*)&sQh[r * AQS + c] = *(const uint4*)&g_qhi[qoff + (size_t)r * D_ + c];
        *(uint4*)&sQl[r * AQS + c] = *(const uint4*)&g_qlo[qoff + (size_t)r * D_ + c];
    }

    float acc[16][4];
    #pragma unroll
    for (int ot = 0; ot < 16; ot++)
        #pragma unroll
        for (int i = 0; i < 4; i++) acc[ot][i] = 0.f;
    float m0 = -1e30f, m1 = -1e30f, l0 = 0.f, l1 = 0.f;

    int nkt = 2 * qt + 2;
    for (int kt = 0; kt < nkt; kt++) {
        __syncthreads();
        size_t koff = kvoff + (size_t)kt * 64 * D_;
        for (int i = tid; i < 1024; i += 256) {
            int r = i >> 4, c = (i & 15) << 3;
            size_t g = koff + (size_t)r * D_ + c;
            int sidx = r * AQS + c;
            *(uint4*)&sKh[sidx] = *(const uint4*)&g_khi[g];
            *(uint4*)&sKl[sidx] = *(const uint4*)&g_klo[g];
            *(uint4*)&sVh[sidx] = *(const uint4*)&g_vhi[g];
            *(uint4*)&sVl[sidx] = *(const uint4*)&g_vlo[g];
        }
        __syncthreads();

        // ---- scores: 16 rows x 64 cols per warp
        float sc[8][4];
        #pragma unroll
        for (int nt = 0; nt < 8; nt++)
            #pragma unroll
            for (int i = 0; i < 4; i++) sc[nt][i] = 0.f;

        #pragma unroll
        for (int kk = 0; kk < 8; kk++) {
            uint32_t ah[4], al[4];
            int qidx = (warp * 16 + (lane & 15)) * AQS + kk * 16 + ((lane >> 4) << 3);
            ldm_x4(ah, smem_u32(&sQh[qidx]));
            ldm_x4(al, smem_u32(&sQl[qidx]));
            #pragma unroll
            for (int nc = 0; nc < 4; nc++) {
                // K tile stored [seq][d] = row-major n x k -> B operand via
                // NON-transposed ldmatrix, rows = seq, cols = d.
                uint32_t kh4[4], kl4[4];
                int kidx = (nc * 16 + (lane & 15)) * AQS + kk * 16 + ((lane >> 4) << 3);
                ldm_x4(kh4, smem_u32(&sKh[kidx]));
                ldm_x4(kl4, smem_u32(&sKl[kidx]));
                // regs: [0]=n0-7/k0-7, [1]=n8-15/k0-7, [2]=n0-7/k8-15, [3]=n8-15/k8-15
                #pragma unroll
                for (int hf = 0; hf < 2; hf++) {
                    int nt = nc * 2 + hf;
                    mma_bf16(sc[nt], ah, kh4[hf], kh4[hf + 2]);
                    mma_bf16(sc[nt], ah, kl4[hf], kl4[hf + 2]);
                    mma_bf16(sc[nt], al, kh4[hf], kh4[hf + 2]);
                }
            }
        }

        // ---- softmax in fragments
        int row0 = qt * 128 + warp * 16 + (lane >> 2);
        int col0 = kt * 64 + ((lane & 3) << 1);
        float ml0 = -1e30f, ml1 = -1e30f;
        #pragma unroll
        for (int nt = 0; nt < 8; nt++) {
            int c0 = col0 + nt * 8;
            float v0 = sc[nt][0] * SCALE_ + ((c0    ) > row0     ? NEG_ : 0.f);
            float v1 = sc[nt][1] * SCALE_ + ((c0 + 1) > row0     ? NEG_ : 0.f);
            float v2 = sc[nt][2] * SCALE_ + ((c0    ) > row0 + 8 ? NEG_ : 0.f);
            float v3 = sc[nt][3] * SCALE_ + ((c0 + 1) > row0 + 8 ? NEG_ : 0.f);
            sc[nt][0] = v0; sc[nt][1] = v1; sc[nt][2] = v2; sc[nt][3] = v3;
            ml0 = fmaxf(ml0, fmaxf(v0, v1));
            ml1 = fmaxf(ml1, fmaxf(v2, v3));
        }
        ml0 = fmaxf(ml0, __shfl_xor_sync(0xffffffffu, ml0, 1));
        ml0 = fmaxf(ml0, __shfl_xor_sync(0xffffffffu, ml0, 2));
        ml1 = fmaxf(ml1, __shfl_xor_sync(0xffffffffu, ml1, 1));
        ml1 = fmaxf(ml1, __shfl_xor_sync(0xffffffffu, ml1, 2));
        float nm0 = fmaxf(m0, ml0), nm1 = fmaxf(m1, ml1);
        float corr0 = __expf(m0 - nm0), corr1 = __expf(m1 - nm1);
        m0 = nm0; m1 = nm1;

        uint32_t ph[8][2], pl[8][2];
        float sum0 = 0.f, sum1 = 0.f;
        #pragma unroll
        for (int nt = 0; nt < 8; nt++) {
            float p0 = __expf(sc[nt][0] - nm0);
            float p1 = __expf(sc[nt][1] - nm0);
            float p2 = __expf(sc[nt][2] - nm1);
            float p3 = __expf(sc[nt][3] - nm1);
            sum0 += p0 + p1; sum1 += p2 + p3;
            __nv_bfloat162 h01 = __floats2bfloat162_rn(p0, p1);
            __nv_bfloat162 h23 = __floats2bfloat162_rn(p2, p3);
            ph[nt][0] = bf2_u32(h01);
            ph[nt][1] = bf2_u32(h23);
            __nv_bfloat162 l01 = __floats2bfloat162_rn(p0 - __bfloat162float(h01.x),
                                                       p1 - __bfloat162float(h01.y));
            __nv_bfloat162 l23 = __floats2bfloat162_rn(p2 - __bfloat162float(h23.x),
                                                       p3 - __bfloat162float(h23.y));
            pl[nt][0] = bf2_u32(l01);
            pl[nt][1] = bf2_u32(l23);
        }
        sum0 += __shfl_xor_sync(0xffffffffu, sum0, 1);
        sum0 += __shfl_xor_sync(0xffffffffu, sum0, 2);
        sum1 += __shfl_xor_sync(0xffffffffu, sum1, 1);
        sum1 += __shfl_xor_sync(0xffffffffu, sum1, 2);
        l0 = l0 * corr0 + sum0;
        l1 = l1 * corr1 + sum1;
        #pragma unroll
        for (int ot = 0; ot < 16; ot++) {
            acc[ot][0] *= corr0; acc[ot][1] *= corr0;
            acc[ot][2] *= corr1; acc[ot][3] *= corr1;
        }

        // ---- PV: V stored [seq][d] = row-major k x n -> trans ldmatrix (as GEMM B)
        #pragma unroll
        for (int k2 = 0; k2 < 4; k2++) {
            uint32_t a0 = ph[2*k2][0], a1 = ph[2*k2][1];
            uint32_t a2 = ph[2*k2+1][0], a3 = ph[2*k2+1][1];
            uint32_t e0 = pl[2*k2][0], e1 = pl[2*k2][1];
            uint32_t e2 = pl[2*k2+1][0], e3 = pl[2*k2+1][1];
            #pragma unroll
            for (int nc = 0; nc < 8; nc++) {
                uint32_t vh4[4], vl4[4];
                int vidx = (k2 * 16 + (lane & 15)) * AQS + nc * 16 + ((lane >> 4) << 3);
                ldm_x4_t(vh4, smem_u32(&sVh[vidx]));
                ldm_x4_t(vl4, smem_u32(&sVl[vidx]));
                #pragma unroll
                for (int hf = 0; hf < 2; hf++) {
                    int ot = nc * 2 + hf, of = hf * 2;
                    mma_bf16_s(acc[ot], a0, a1, a2, a3, vh4[of], vh4[of + 1]);
                    mma_bf16_s(acc[ot], a0, a1, a2, a3, vl4[of], vl4[of + 1]);
                    mma_bf16_s(acc[ot], e0, e1, e2, e3, vh4[of], vh4[of + 1]);
                }
            }
        }
    }

    // ---- epilogue: normalize, gate, write g_gated
    float inv0 = 1.f / l0, inv1 = 1.f / l1;
    int srow = qt * 128 + warp * 16 + (lane >> 2);
    #pragma unroll
    for (int rp = 0; rp < 2; rp++) {
        int s = srow + rp * 8;
        size_t bs = (size_t)b * S_ + s;
        float inv = rp ? inv1 : inv0;
        #pragma unroll
        for (int ot = 0; ot < 16; ot++) {
            int c0 = ot * 8 + ((lane & 3) << 1);
            float2 g2 = *(const float2*)&g_qg[bs * (size_t)(H_*2*D_) + h * (2*D_) + D_ + c0];
            float o0 = acc[ot][rp*2    ] * inv * (1.f / (1.f + __expf(-g2.x)));
            float o1 = acc[ot][rp*2 + 1] * inv * (1.f / (1.f + __expf(-g2.y)));
            *(float2*)&g_gated[bs * (size_t)(H_*D_) + h * D_ + c0] = make_float2(o0, o1);
        }
    }
}

// ---------------- launch ----------------------------------------------------
extern "C" void kernel_launch(void* const* d_in, const int* in_sizes, int n_in,
                              void* d_out, int out_size) {
    const float* hidden = (const float*)d_in[0];
    const float* cosb   = (const float*)d_in[1];
    const float* sinb   = (const float*)d_in[2];
    // d_in[3] = attention_mask (pure causal; computed arithmetically)
    const float* wq     = (const float*)d_in[4];
    const float* wk     = (const float*)d_in[5];
    const float* wv     = (const float*)d_in[6];
    const float* wo     = (const float*)d_in[7];
    const float* qnw    = (const float*)d_in[8];
    const float* knw    = (const float*)d_in[9];
    float* out = (float*)d_out;

    float *qg, *kproj, *vproj, *gated;
    cudaGetSymbolAddress((void**)&qg,    g_qg);
    cudaGetSymbolAddress((void**)&kproj, g_kproj);
    cudaGetSymbolAddress((void**)&vproj, g_vproj);
    cudaGetSymbolAddress((void**)&gated, g_gated);

    cudaFuncSetAttribute(attn_mma_kernel,
                         cudaFuncAttributeMaxDynamicSharedMemorySize, ATT_SMEM);

    const int M = B_ * S_;   // 8192

    // projections (tensor-core bf16x3)
    gemm_bf16x3<<<dim3((H_*2*D_)/BN, M/BM), 256>>>(hidden, wq, qg,    M, H_*2*D_, HID_);
    gemm_bf16x3<<<dim3((KV_*D_)/BN,  M/BM), 256>>>(hidden, wk, kproj, M, KV_*D_,  HID_);
    gemm_bf16x3<<<dim3((KV_*D_)/BN,  M/BM), 256>>>(hidden, wv, vproj, M, KV_*D_,  HID_);

    // norms + rope -> bf16 hi/lo
    qnorm_rope_kernel  <<<dim3(M, H_),  128>>>(cosb, sinb, qnw);
    knorm_rope_v_kernel<<<dim3(M, KV_), 128>>>(cosb, sinb, knw);

    // tensor-core attention (+ fused sigmoid gate)
    attn_mma_kernel<<<dim3(B_*H_, S_/128), 256, ATT_SMEM>>>();

    // output projection
    gemm_bf16x3<<<dim3(HID_/BN, M/BM), 256>>>(gated, wo, out, M, HID_, H_*D_);
}

// round 5
// speedup vs baseline: 2.7966x; 1.2101x over previous
#include <cuda_runtime.h>
#include <cuda_bf16.h>
#include <math.h>
#include <stdint.h>

#define B_ 4
#define S_ 2048
#define HID_ 2048
#define H_ 16
#define KV_ 4
#define D_ 128
#define ROT_ 32
#define GROUPS_ (H_/KV_)
#define NEG_ (-1000000000.0f)
#define SCALE_ 0.08838834764831845f   // D^-0.5

// ---------------- scratch (device globals; no allocations allowed) ----------
__device__ float g_qg   [(size_t)B_*S_*H_*2*D_];   // [B*S, H*2D]  q|gate
__device__ float g_kproj[(size_t)B_*S_*KV_*D_];    // [B*S, KV*D]
__device__ float g_vproj[(size_t)B_*S_*KV_*D_];    // [B*S, KV*D]
__device__ __nv_bfloat16 g_hhi[(size_t)B_*S_*HID_];
__device__ __nv_bfloat16 g_hlo[(size_t)B_*S_*HID_];
__device__ __nv_bfloat16 g_wqhi[(size_t)HID_*H_*2*D_];
__device__ __nv_bfloat16 g_wqlo[(size_t)HID_*H_*2*D_];
__device__ __nv_bfloat16 g_wkhi[(size_t)HID_*KV_*D_];
__device__ __nv_bfloat16 g_wklo[(size_t)HID_*KV_*D_];
__device__ __nv_bfloat16 g_wvhi[(size_t)HID_*KV_*D_];
__device__ __nv_bfloat16 g_wvlo[(size_t)HID_*KV_*D_];
__device__ __nv_bfloat16 g_wohi[(size_t)H_*D_*HID_];
__device__ __nv_bfloat16 g_wolo[(size_t)H_*D_*HID_];
__device__ __nv_bfloat16 g_qhi[(size_t)B_*H_*S_*D_];
__device__ __nv_bfloat16 g_qlo[(size_t)B_*H_*S_*D_];
__device__ __nv_bfloat16 g_khi[(size_t)B_*KV_*S_*D_];
__device__ __nv_bfloat16 g_klo[(size_t)B_*KV_*S_*D_];
__device__ __nv_bfloat16 g_vhi[(size_t)B_*KV_*S_*D_];
__device__ __nv_bfloat16 g_vlo[(size_t)B_*KV_*S_*D_];
__device__ __nv_bfloat16 g_ghi[(size_t)B_*S_*H_*D_];   // gated attn hi
__device__ __nv_bfloat16 g_glo[(size_t)B_*S_*H_*D_];   // gated attn lo

// ---------------- mma helpers ------------------------------------------------
__device__ __forceinline__ uint32_t smem_u32(const void* p) {
    return (uint32_t)__cvta_generic_to_shared(p);
}
__device__ __forceinline__ void ldm_x4(uint32_t* r, uint32_t addr) {
    asm volatile("ldmatrix.sync.aligned.m8n8.x4.shared.b16 {%0,%1,%2,%3}, [%4];\n"
                 : "=r"(r[0]), "=r"(r[1]), "=r"(r[2]), "=r"(r[3]) : "r"(addr));
}
__device__ __forceinline__ void ldm_x4_t(uint32_t* r, uint32_t addr) {
    asm volatile("ldmatrix.sync.aligned.m8n8.x4.trans.shared.b16 {%0,%1,%2,%3}, [%4];\n"
                 : "=r"(r[0]), "=r"(r[1]), "=r"(r[2]), "=r"(r[3]) : "r"(addr));
}
__device__ __forceinline__ void mma_bf16(float* c, const uint32_t* a,
                                         uint32_t b0, uint32_t b1) {
    asm volatile(
        "mma.sync.aligned.m16n8k16.row.col.f32.bf16.bf16.f32 "
        "{%0,%1,%2,%3}, {%4,%5,%6,%7}, {%8,%9}, {%0,%1,%2,%3};\n"
        : "+f"(c[0]), "+f"(c[1]), "+f"(c[2]), "+f"(c[3])
        : "r"(a[0]), "r"(a[1]), "r"(a[2]), "r"(a[3]), "r"(b0), "r"(b1));
}
__device__ __forceinline__ void mma_bf16_s(float* c, uint32_t a0, uint32_t a1,
                                           uint32_t a2, uint32_t a3,
                                           uint32_t b0, uint32_t b1) {
    asm volatile(
        "mma.sync.aligned.m16n8k16.row.col.f32.bf16.bf16.f32 "
        "{%0,%1,%2,%3}, {%4,%5,%6,%7}, {%8,%9}, {%0,%1,%2,%3};\n"
        : "+f"(c[0]), "+f"(c[1]), "+f"(c[2]), "+f"(c[3])
        : "r"(a0), "r"(a1), "r"(a2), "r"(a3), "r"(b0), "r"(b1));
}
__device__ __forceinline__ uint32_t bf2_u32(__nv_bfloat162 v) {
    return *reinterpret_cast<uint32_t*>(&v);
}
__device__ __forceinline__ void cpa16(uint32_t dst, const void* src) {
    asm volatile("cp.async.cg.shared.global [%0], [%1], 16;\n"
                 :: "r"(dst), "l"(src));
}

// ---------------- split fp32 -> bf16 hi/lo -----------------------------------
__global__ __launch_bounds__(256)
void split_kernel(const float* __restrict__ src, __nv_bfloat16* __restrict__ hi,
                  __nv_bfloat16* __restrict__ lo) {
    size_t i = (size_t)blockIdx.x * 256 + threadIdx.x;   // float4 index
    float4 v = ((const float4*)src)[i];
    __nv_bfloat162 h0 = __floats2bfloat162_rn(v.x, v.y);
    __nv_bfloat162 h1 = __floats2bfloat162_rn(v.z, v.w);
    __nv_bfloat162 l0 = __floats2bfloat162_rn(v.x - __bfloat162float(h0.x),
                                              v.y - __bfloat162float(h0.y));
    __nv_bfloat162 l1 = __floats2bfloat162_rn(v.z - __bfloat162float(h1.x),
                                              v.w - __bfloat162float(h1.y));
    uint2 hw = make_uint2(bf2_u32(h0), bf2_u32(h1));
    uint2 lw = make_uint2(bf2_u32(l0), bf2_u32(l1));
    ((uint2*)hi)[i] = hw;
    ((uint2*)lo)[i] = lw;
}

// ---------------- bf16x3 tensor-core GEMM, pre-split inputs, cp.async -------
// C[M,N] = A[M,K] @ B[K,N]. Block 128x128x32, 256 thr, 2-stage pipeline.
#define ASTR 40
#define BSTR 136
#define A_ELE (128*ASTR)          // 5120
#define B_ELE (32*BSTR)           // 4352
#define STG_ELE (2*A_ELE + 2*B_ELE)   // 18944 bf16 elements per stage
#define GSMEM (2*STG_ELE*2)       // bytes

__global__ __launch_bounds__(256)
void gemm_bf16p(const __nv_bfloat16* __restrict__ Ahi, const __nv_bfloat16* __restrict__ Alo,
                const __nv_bfloat16* __restrict__ Bhi, const __nv_bfloat16* __restrict__ Blo,
                float* __restrict__ C, int M, int N, int K) {
    extern __shared__ __nv_bfloat16 gsm[];
    int tid = threadIdx.x;
    int warp = tid >> 5, lane = tid & 31;
    int wm = (warp >> 2) * 64;
    int wn = (warp & 3) * 32;

    const __nv_bfloat16* Abh = Ahi + (size_t)blockIdx.y * 128 * K;
    const __nv_bfloat16* Abl = Alo + (size_t)blockIdx.y * 128 * K;
    const __nv_bfloat16* Bbh = Bhi + (size_t)blockIdx.x * 128;
    const __nv_bfloat16* Bbl = Blo + (size_t)blockIdx.x * 128;

    float acc[4][4][4];
    #pragma unroll
    for (int mt = 0; mt < 4; mt++)
        #pragma unroll
        for (int nt = 0; nt < 4; nt++)
            #pragma unroll
            for (int i = 0; i < 4; i++) acc[mt][nt][i] = 0.f;

    int KT = K >> 5;

    // issue stage copies for k-tile kt into stage buffer st
    auto issue = [&](int kt, int st) {
        __nv_bfloat16* s = gsm + st * STG_ELE;
        int k0 = kt << 5;
        #pragma unroll
        for (int c = tid; c < 512; c += 256) {          // A: 128 rows x 4 chunks
            int row = c >> 2, col = (c & 3) << 3;
            size_t g = (size_t)row * K + k0 + col;
            cpa16(smem_u32(s + row * ASTR + col), Abh + g);
            cpa16(smem_u32(s + A_ELE + row * ASTR + col), Abl + g);
        }
        #pragma unroll
        for (int c = tid; c < 512; c += 256) {          // B: 32 rows x 16 chunks
            int row = c >> 4, col = (c & 15) << 3;
            size_t g = (size_t)(k0 + row) * N + col;
            cpa16(smem_u32(s + 2*A_ELE + row * BSTR + col), Bbh + g);
            cpa16(smem_u32(s + 2*A_ELE + B_ELE + row * BSTR + col), Bbl + g);
        }
        asm volatile("cp.async.commit_group;\n" ::: "memory");
    };

    issue(0, 0);
    for (int kt = 0; kt < KT; kt++) {
        asm volatile("cp.async.wait_group 0;\n" ::: "memory");
        __syncthreads();
        if (kt + 1 < KT) issue(kt + 1, (kt + 1) & 1);

        __nv_bfloat16* s = gsm + (kt & 1) * STG_ELE;
        __nv_bfloat16* sAhi = s;
        __nv_bfloat16* sAlo = s + A_ELE;
        __nv_bfloat16* sBhi = s + 2*A_ELE;
        __nv_bfloat16* sBlo = s + 2*A_ELE + B_ELE;

        #pragma unroll
        for (int ks = 0; ks < 2; ks++) {
            int kk = ks * 16;
            uint32_t ahi[4][4], alo[4][4];
            #pragma unroll
            for (int mt = 0; mt < 4; mt++) {
                int row = wm + mt * 16 + (lane & 15);
                int col = kk + ((lane >> 4) << 3);
                ldm_x4(ahi[mt], smem_u32(&sAhi[row * ASTR + col]));
                ldm_x4(alo[mt], smem_u32(&sAlo[row * ASTR + col]));
            }
            uint32_t bhi[2][4], blo[2][4];
            #pragma unroll
            for (int nc = 0; nc < 2; nc++) {
                int row = kk + (lane & 15);
                int col = wn + nc * 16 + ((lane >> 4) << 3);
                ldm_x4_t(bhi[nc], smem_u32(&sBhi[row * BSTR + col]));
                ldm_x4_t(blo[nc], smem_u32(&sBlo[row * BSTR + col]));
            }
            #pragma unroll
            for (int mt = 0; mt < 4; mt++) {
                #pragma unroll
                for (int nt = 0; nt < 4; nt++) {
                    int nc = nt >> 1, off = (nt & 1) << 1;
                    mma_bf16(acc[mt][nt], ahi[mt], bhi[nc][off], bhi[nc][off + 1]);
                    mma_bf16(acc[mt][nt], ahi[mt], blo[nc][off], blo[nc][off + 1]);
                    mma_bf16(acc[mt][nt], alo[mt], bhi[nc][off], bhi[nc][off + 1]);
                }
            }
        }
        __syncthreads();
    }

    float* Cb = C + (size_t)blockIdx.y * 128 * N + (size_t)blockIdx.x * 128;
    #pragma unroll
    for (int mt = 0; mt < 4; mt++) {
        #pragma unroll
        for (int nt = 0; nt < 4; nt++) {
            int r = wm + mt * 16 + (lane >> 2);
            int c = wn + nt * 8 + ((lane & 3) << 1);
            *(float2*)&Cb[(size_t)r * N + c] = make_float2(acc[mt][nt][0], acc[mt][nt][1]);
            *(float2*)&Cb[(size_t)(r + 8) * N + c] = make_float2(acc[mt][nt][2], acc[mt][nt][3]);
        }
    }
}

// ---------------- RMSNorm + RoPE for Q -> bf16 hi/lo (loop over heads) ------
__global__ __launch_bounds__(128)
void qnorm_rope_kernel(const float* __restrict__ cosb, const float* __restrict__ sinb,
                       const float* __restrict__ w) {
    int bs = blockIdx.x, d = threadIdx.x;
    float wd = 1.f + w[d];
    float cthis = 0.f, sthis = 0.f;
    if (d < ROT_) {
        cthis = cosb[(size_t)bs * ROT_ + d];
        sthis = sinb[(size_t)bs * ROT_ + d];
    }
    int b = bs / S_, s = bs % S_;
    int warp = d >> 5, lane = d & 31;
    __shared__ float ws[4];

    for (int h = 0; h < H_; h++) {
        float x = g_qg[(size_t)bs * (H_*2*D_) + h * (2*D_) + d];
        float v = x * x;
        #pragma unroll
        for (int off = 16; off; off >>= 1) v += __shfl_xor_sync(0xffffffffu, v, off);
        if (lane == 0) ws[warp] = v;
        __syncthreads();
        float tot = ws[0] + ws[1] + ws[2] + ws[3];
        __syncthreads();

        float xn = x * rsqrtf(tot * (1.f/128.f) + 1e-6f) * wd;
        float o = xn;
        if (d < ROT_) {
            float xp = __shfl_xor_sync(0xffffffffu, xn, 16);
            float rot = (d < 16) ? -xp : xp;
            o = xn * cthis + rot * sthis;
        }
        size_t idx = (((size_t)b * H_ + h) * S_ + s) * D_ + d;
        __nv_bfloat16 hi = __float2bfloat16(o);
        g_qhi[idx] = hi;
        g_qlo[idx] = __float2bfloat16(o - __bfloat162float(hi));
    }
}

// ---------------- RMSNorm + RoPE for K, V -> bf16 hi/lo ---------------------
__global__ __launch_bounds__(128)
void knorm_rope_v_kernel(const float* __restrict__ cosb, const float* __restrict__ sinb,
                         const float* __restrict__ w) {
    int bs = blockIdx.x, d = threadIdx.x;
    float wd = 1.f + w[d];
    float cthis = 0.f, sthis = 0.f;
    if (d < ROT_) {
        cthis = cosb[(size_t)bs * ROT_ + d];
        sthis = sinb[(size_t)bs * ROT_ + d];
    }
    int b = bs / S_, s = bs % S_;
    int warp = d >> 5, lane = d & 31;
    __shared__ float ws[4];

    for (int kv = 0; kv < KV_; kv++) {
        size_t iidx = (size_t)bs * (KV_*D_) + kv * D_ + d;
        float x = g_kproj[iidx];
        float v = x * x;
        #pragma unroll
        for (int off = 16; off; off >>= 1) v += __shfl_xor_sync(0xffffffffu, v, off);
        if (lane == 0) ws[warp] = v;
        __syncthreads();
        float tot = ws[0] + ws[1] + ws[2] + ws[3];
        __syncthreads();

        float xn = x * rsqrtf(tot * (1.f/128.f) + 1e-6f) * wd;
        float o = xn;
        if (d < ROT_) {
            float xp = __shfl_xor_sync(0xffffffffu, xn, 16);
            float rot = (d < 16) ? -xp : xp;
            o = xn * cthis + rot * sthis;
        }
        size_t oidx = (((size_t)b * KV_ + kv) * S_ + s) * D_ + d;
        __nv_bfloat16 khi = __float2bfloat16(o);
        g_khi[oidx] = khi;
        g_klo[oidx] = __float2bfloat16(o - __bfloat162float(khi));
        float vv = g_vproj[iidx];
        __nv_bfloat16 vhi = __float2bfloat16(vv);
        g_vhi[oidx] = vhi;
        g_vlo[oidx] = __float2bfloat16(vv - __bfloat162float(vhi));
    }
}

// ---------------- tensor-core flash attention (causal, GQA) -----------------
#define AQS 136
#define ATT_SMEM ((2*128*AQS + 4*64*AQS) * 2)   // bytes (bf16)

__global__ __launch_bounds__(256)
void attn_mma_kernel() {
    extern __shared__ __align__(16) __nv_bfloat16 smA[];
    __nv_bfloat16* sQh = smA;
    __nv_bfloat16* sQl = sQh + 128 * AQS;
    __nv_bfloat16* sKh = sQl + 128 * AQS;
    __nv_bfloat16* sKl = sKh + 64 * AQS;
    __nv_bfloat16* sVh = sKl + 64 * AQS;
    __nv_bfloat16* sVl = sVh + 64 * AQS;

    int tid = threadIdx.x, warp = tid >> 5, lane = tid & 31;
    int bh = blockIdx.x, qt = blockIdx.y;
    int b = bh >> 4, h = bh & 15, kvh = h >> 2;

    size_t qoff = ((size_t)bh * S_ + (size_t)qt * 128) * D_;
    size_t kvoff = ((size_t)(b * KV_ + kvh) * S_) * D_;

    for (int i = tid; i < 2048; i += 256) {
        int r = i >> 4, c = (i & 15) << 3;
        *(uint4*)&sQh[r * AQS + c] = *(const uint4*)&g_qhi[qoff + (size_t)r * D_ + c];
        *(uint4*)&sQl[r * AQS + c] = *(const uint4*)&g_qlo[qoff + (size_t)r * D_ + c];
    }

    float acc[16][4];
    #pragma unroll
    for (int ot = 0; ot < 16; ot++)
        #pragma unroll
        for (int i = 0; i < 4; i++) acc[ot][i] = 0.f;
    float m0 = -1e30f, m1 = -1e30f, l0 = 0.f, l1 = 0.f;

    int nkt = 2 * qt + 2;
    for (int kt = 0; kt < nkt; kt++) {
        __syncthreads();
        size_t koff = kvoff + (size_t)kt * 64 * D_;
        for (int i = tid; i < 1024; i += 256) {
            int r = i >> 4, c = (i & 15) << 3;
            size_t g = koff + (size_t)r * D_ + c;
            int sidx = r * AQS + c;
            *(uint4*)&sKh[sidx] = *(const uint4*)&g_khi[g];
            *(uint4*)&sKl[sidx] = *(const uint4*)&g_klo[g];
            *(uint4*)&sVh[sidx] = *(const uint4*)&g_vhi[g];
            *(uint4*)&sVl[sidx] = *(const uint4*)&g_vlo[g];
        }
        __syncthreads();

        float sc[8][4];
        #pragma unroll
        for (int nt = 0; nt < 8; nt++)
            #pragma unroll
            for (int i = 0; i < 4; i++) sc[nt][i] = 0.f;

        #pragma unroll
        for (int kk = 0; kk < 8; kk++) {
            uint32_t ah[4], al[4];
            int qidx = (warp * 16 + (lane & 15)) * AQS + kk * 16 + ((lane >> 4) << 3);
            ldm_x4(ah, smem_u32(&sQh[qidx]));
            ldm_x4(al, smem_u32(&sQl[qidx]));
            #pragma unroll
            for (int nc = 0; nc < 4; nc++) {
                uint32_t kh4[4], kl4[4];
                int kidx = (nc * 16 + (lane & 15)) * AQS + kk * 16 + ((lane >> 4) << 3);
                ldm_x4(kh4, smem_u32(&sKh[kidx]));
                ldm_x4(kl4, smem_u32(&sKl[kidx]));
                #pragma unroll
                for (int hf = 0; hf < 2; hf++) {
                    int nt = nc * 2 + hf;
                    mma_bf16(sc[nt], ah, kh4[hf], kh4[hf + 2]);
                    mma_bf16(sc[nt], ah, kl4[hf], kl4[hf + 2]);
                    mma_bf16(sc[nt], al, kh4[hf], kh4[hf + 2]);
                }
            }
        }

        int row0 = qt * 128 + warp * 16 + (lane >> 2);
        int col0 = kt * 64 + ((lane & 3) << 1);
        float ml0 = -1e30f, ml1 = -1e30f;
        #pragma unroll
        for (int nt = 0; nt < 8; nt++) {
            int c0 = col0 + nt * 8;
            float v0 = sc[nt][0] * SCALE_ + ((c0    ) > row0     ? NEG_ : 0.f);
            float v1 = sc[nt][1] * SCALE_ + ((c0 + 1) > row0     ? NEG_ : 0.f);
            float v2 = sc[nt][2] * SCALE_ + ((c0    ) > row0 + 8 ? NEG_ : 0.f);
            float v3 = sc[nt][3] * SCALE_ + ((c0 + 1) > row0 + 8 ? NEG_ : 0.f);
            sc[nt][0] = v0; sc[nt][1] = v1; sc[nt][2] = v2; sc[nt][3] = v3;
            ml0 = fmaxf(ml0, fmaxf(v0, v1));
            ml1 = fmaxf(ml1, fmaxf(v2, v3));
        }
        ml0 = fmaxf(ml0, __shfl_xor_sync(0xffffffffu, ml0, 1));
        ml0 = fmaxf(ml0, __shfl_xor_sync(0xffffffffu, ml0, 2));
        ml1 = fmaxf(ml1, __shfl_xor_sync(0xffffffffu, ml1, 1));
        ml1 = fmaxf(ml1, __shfl_xor_sync(0xffffffffu, ml1, 2));
        float nm0 = fmaxf(m0, ml0), nm1 = fmaxf(m1, ml1);
        float corr0 = __expf(m0 - nm0), corr1 = __expf(m1 - nm1);
        m0 = nm0; m1 = nm1;

        uint32_t ph[8][2], pl[8][2];
        float sum0 = 0.f, sum1 = 0.f;
        #pragma unroll
        for (int nt = 0; nt < 8; nt++) {
            float p0 = __expf(sc[nt][0] - nm0);
            float p1 = __expf(sc[nt][1] - nm0);
            float p2 = __expf(sc[nt][2] - nm1);
            float p3 = __expf(sc[nt][3] - nm1);
            sum0 += p0 + p1; sum1 += p2 + p3;
            __nv_bfloat162 h01 = __floats2bfloat162_rn(p0, p1);
            __nv_bfloat162 h23 = __floats2bfloat162_rn(p2, p3);
            ph[nt][0] = bf2_u32(h01);
            ph[nt][1] = bf2_u32(h23);
            __nv_bfloat162 l01 = __floats2bfloat162_rn(p0 - __bfloat162float(h01.x),
                                                       p1 - __bfloat162float(h01.y));
            __nv_bfloat162 l23 = __floats2bfloat162_rn(p2 - __bfloat162float(h23.x),
                                                       p3 - __bfloat162float(h23.y));
            pl[nt][0] = bf2_u32(l01);
            pl[nt][1] = bf2_u32(l23);
        }
        sum0 += __shfl_xor_sync(0xffffffffu, sum0, 1);
        sum0 += __shfl_xor_sync(0xffffffffu, sum0, 2);
        sum1 += __shfl_xor_sync(0xffffffffu, sum1, 1);
        sum1 += __shfl_xor_sync(0xffffffffu, sum1, 2);
        l0 = l0 * corr0 + sum0;
        l1 = l1 * corr1 + sum1;
        #pragma unroll
        for (int ot = 0; ot < 16; ot++) {
            acc[ot][0] *= corr0; acc[ot][1] *= corr0;
            acc[ot][2] *= corr1; acc[ot][3] *= corr1;
        }

        #pragma unroll
        for (int k2 = 0; k2 < 4; k2++) {
            uint32_t a0 = ph[2*k2][0], a1 = ph[2*k2][1];
            uint32_t a2 = ph[2*k2+1][0], a3 = ph[2*k2+1][1];
            uint32_t e0 = pl[2*k2][0], e1 = pl[2*k2][1];
            uint32_t e2 = pl[2*k2+1][0], e3 = pl[2*k2+1][1];
            #pragma unroll
            for (int nc = 0; nc < 8; nc++) {
                uint32_t vh4[4], vl4[4];
                int vidx = (k2 * 16 + (lane & 15)) * AQS + nc * 16 + ((lane >> 4) << 3);
                ldm_x4_t(vh4, smem_u32(&sVh[vidx]));
                ldm_x4_t(vl4, smem_u32(&sVl[vidx]));
                #pragma unroll
                for (int hf = 0; hf < 2; hf++) {
                    int ot = nc * 2 + hf, of = hf * 2;
                    mma_bf16_s(acc[ot], a0, a1, a2, a3, vh4[of], vh4[of + 1]);
                    mma_bf16_s(acc[ot], a0, a1, a2, a3, vl4[of], vl4[of + 1]);
                    mma_bf16_s(acc[ot], e0, e1, e2, e3, vh4[of], vh4[of + 1]);
                }
            }
        }
    }

    // ---- epilogue: normalize, gate, write bf16 hi/lo gated output
    float inv0 = 1.f / l0, inv1 = 1.f / l1;
    int srow = qt * 128 + warp * 16 + (lane >> 2);
    #pragma unroll
    for (int rp = 0; rp < 2; rp++) {
        int s = srow + rp * 8;
        size_t bs = (size_t)b * S_ + s;
        float inv = rp ? inv1 : inv0;
        #pragma unroll
        for (int ot = 0; ot < 16; ot++) {
            int c0 = ot * 8 + ((lane & 3) << 1);
            float2 g2 = *(const float2*)&g_qg[bs * (size_t)(H_*2*D_) + h * (2*D_) + D_ + c0];
            float o0 = acc[ot][rp*2    ] * inv * (1.f / (1.f + __expf(-g2.x)));
            float o1 = acc[ot][rp*2 + 1] * inv * (1.f / (1.f + __expf(-g2.y)));
            __nv_bfloat162 hi2 = __floats2bfloat162_rn(o0, o1);
            __nv_bfloat162 lo2 = __floats2bfloat162_rn(o0 - __bfloat162float(hi2.x),
                                                       o1 - __bfloat162float(hi2.y));
            size_t oi = bs * (size_t)(H_*D_) + h * D_ + c0;
            *(uint32_t*)&g_ghi[oi] = bf2_u32(hi2);
            *(uint32_t*)&g_glo[oi] = bf2_u32(lo2);
        }
    }
}

// ---------------- launch ----------------------------------------------------
extern "C" void kernel_launch(void* const* d_in, const int* in_sizes, int n_in,
                              void* d_out, int out_size) {
    const float* hidden = (const float*)d_in[0];
    const float* cosb   = (const float*)d_in[1];
    const float* sinb   = (const float*)d_in[2];
    // d_in[3] = attention_mask (pure causal; computed arithmetically)
    const float* wq     = (const float*)d_in[4];
    const float* wk     = (const float*)d_in[5];
    const float* wv     = (const float*)d_in[6];
    const float* wo     = (const float*)d_in[7];
    const float* qnw    = (const float*)d_in[8];
    const float* knw    = (const float*)d_in[9];
    float* out = (float*)d_out;

    float *qg, *kproj, *vproj;
    cudaGetSymbolAddress((void**)&qg,    g_qg);
    cudaGetSymbolAddress((void**)&kproj, g_kproj);
    cudaGetSymbolAddress((void**)&vproj, g_vproj);
    __nv_bfloat16 *hhi, *hlo, *wqhi, *wqlo, *wkhi, *wklo, *wvhi, *wvlo, *wohi, *wolo, *ghi, *glo;
    cudaGetSymbolAddress((void**)&hhi,  g_hhi);
    cudaGetSymbolAddress((void**)&hlo,  g_hlo);
    cudaGetSymbolAddress((void**)&wqhi, g_wqhi);
    cudaGetSymbolAddress((void**)&wqlo, g_wqlo);
    cudaGetSymbolAddress((void**)&wkhi, g_wkhi);
    cudaGetSymbolAddress((void**)&wklo, g_wklo);
    cudaGetSymbolAddress((void**)&wvhi, g_wvhi);
    cudaGetSymbolAddress((void**)&wvlo, g_wvlo);
    cudaGetSymbolAddress((void**)&wohi, g_wohi);
    cudaGetSymbolAddress((void**)&wolo, g_wolo);
    cudaGetSymbolAddress((void**)&ghi,  g_ghi);
    cudaGetSymbolAddress((void**)&glo,  g_glo);

    cudaFuncSetAttribute(attn_mma_kernel,
                         cudaFuncAttributeMaxDynamicSharedMemorySize, ATT_SMEM);
    cudaFuncSetAttribute(gemm_bf16p,
                         cudaFuncAttributeMaxDynamicSharedMemorySize, GSMEM);

    const int M = B_ * S_;   // 8192

    // pre-split fp32 -> bf16 hi/lo
    split_kernel<<<(B_*S_*HID_)/1024, 256>>>(hidden, hhi, hlo);
    split_kernel<<<(HID_*H_*2*D_)/1024, 256>>>(wq, wqhi, wqlo);
    split_kernel<<<(HID_*KV_*D_)/1024, 256>>>(wk, wkhi, wklo);
    split_kernel<<<(HID_*KV_*D_)/1024, 256>>>(wv, wvhi, wvlo);
    split_kernel<<<(H_*D_*HID_)/1024, 256>>>(wo, wohi, wolo);

    // projections
    gemm_bf16p<<<dim3((H_*2*D_)/128, M/128), 256, GSMEM>>>(hhi, hlo, wqhi, wqlo, qg, M, H_*2*D_, HID_);
    gemm_bf16p<<<dim3((KV_*D_)/128,  M/128), 256, GSMEM>>>(hhi, hlo, wkhi, wklo, kproj, M, KV_*D_, HID_);
    gemm_bf16p<<<dim3((KV_*D_)/128,  M/128), 256, GSMEM>>>(hhi, hlo, wvhi, wvlo, vproj, M, KV_*D_, HID_);

    // norms + rope -> bf16 hi/lo
    qnorm_rope_kernel  <<<M, 128>>>(cosb, sinb, qnw);
    knorm_rope_v_kernel<<<M, 128>>>(cosb, sinb, knw);

    // tensor-core attention (+ fused sigmoid gate, bf16 hi/lo out)
    attn_mma_kernel<<<dim3(B_*H_, S_/128), 256, ATT_SMEM>>>();

    // output projection
    gemm_bf16p<<<dim3(HID_/128, M/128), 256, GSMEM>>>(ghi, glo, wohi, wolo, out, M, HID_, H_*D_);
}